// round 14
// baseline (speedup 1.0000x reference)
#include <cuda_runtime.h>
#include <cuda_fp16.h>
#include <cstdint>

// ============================================================
// Conv2d 3x3 s1 p1: x(32,128,56,56)*W(256,128,3,3)+b -> (32,256,56,56)
// Shifted-GEMM conv on mma.sync.m16n8k16.f32.f16.f16.f32.
// R14 = R12 (best variant, conv 151.1us) with:
//  - staging spread across the window: B round r0+j staged just before
//    compute round 4w+j (one commit per window, all post-barrier; ring
//    safety identical to R12)
//  - prep interior copy at 32B/thread (half the threads/index math)
// Warp tile 32x64 (192 B/HMMA, the crossbar/occupancy optimum found in
// R13's post-mortem). 9 quad windows, B ring of 2, A double-buffered.
// CTA = 128 px x 128 couts, 256 thr, 2 CTAs/SM.
// ============================================================

#define HW        56
#define PW        58
#define CSTRIDE   3584          // half2 units per (b,c2) slice
#define CIN       128
#define COUT      256
#define BATCH     32
#define MTILES    26
#define NWIN      9             // 36 shift-rounds as 9 quad windows
#define AQ        248           // A smem q-stride (half2 units)
#define SA_BYTES  (16 * AQ * 4) // 15872 per A buffer
#define ABUFS     (2 * SA_BYTES)
#define SBQ_BYTES 32768         // B quad buffer (4 rounds x 8KB)
#define SMEM_TOTAL (ABUFS + 2 * SBQ_BYTES)   // 97280

__device__ __half2  g_xpadh[BATCH * 64 * CSTRIDE];   // zero-init at load;
                                                     // border/slack never written
__device__ uint32_t g_wrfh[2 * 4 * 9 * 2048];        // W fragment order (half2)

#define N_COPY (32 * 64 * 56 * 7)   // 32B of output per thread
#define N_WRF  (2 * 4 * 9 * 2048)

// ---------------- fused prep: interior copy + W fragments ----------------
__global__ void prep_kernel(const float* __restrict__ x, const float* __restrict__ W) {
    int id = blockIdx.x * blockDim.x + threadIdx.x;
    if (id < N_COPY) {
        int f8  = id % 7;                  // 8-float column block (56 = 7*8)
        int h   = (id / 7) % 56;
        int bc2 = id / (7 * 56);           // b*64 + c2
        const float* p0 = x + ((long)bc2 * 2) * 3136 + h * 56 + f8 * 8;
        float4 a0 = *(const float4*)p0;
        float4 a1 = *(const float4*)(p0 + 4);
        float4 b0 = *(const float4*)(p0 + 3136);
        float4 b1 = *(const float4*)(p0 + 3140);
        __half2* d = g_xpadh + (long)bc2 * CSTRIDE + (h + 1) * PW + 1 + f8 * 8;
        d[0] = __floats2half2_rn(a0.x, b0.x);
        d[1] = __floats2half2_rn(a0.y, b0.y);
        d[2] = __floats2half2_rn(a0.z, b0.z);
        d[3] = __floats2half2_rn(a0.w, b0.w);
        d[4] = __floats2half2_rn(a1.x, b1.x);
        d[5] = __floats2half2_rn(a1.y, b1.y);
        d[6] = __floats2half2_rn(a1.z, b1.z);
        d[7] = __floats2half2_rn(a1.w, b1.w);
    } else if (id < N_COPY + N_WRF) {
        // g_wrfh: block = (nb*4+chunk)*9+s, u4 = ((p*2+kt)*32+lane), word j:
        //   nt = p*2+(j>>1), reg = j&1
        //   half2 = (W[n][c], W[n][c+1]), n = nb*128+nt*8+lane/4,
        //   c = chunk*32 + kt*16 + (lane&3)*2 + reg*8
        int idx3 = id - N_COPY;
        int blk = idx3 >> 11, within = idx3 & 2047;
        int s = blk % 9, t = blk / 9;
        int chunk = t & 3, nb = t >> 2;
        int u4 = within >> 2, j = within & 3;
        int lane = u4 & 31, t2 = u4 >> 5;
        int kt = t2 & 1, p = t2 >> 1;
        int nt = p * 2 + (j >> 1), reg = j & 1;
        int n = nb * 128 + nt * 8 + (lane >> 2);
        int c = chunk * 32 + kt * 16 + (lane & 3) * 2 + reg * 8;
        __half2 hv = __floats2half2_rn(W[(n * CIN + c) * 9 + s],
                                       W[(n * CIN + c + 1) * 9 + s]);
        g_wrfh[idx3] = *(uint32_t*)&hv;
    }
}

// ---------------- helpers ----------------
__device__ __forceinline__ void mma_f16(float* d, const uint32_t* a, const uint32_t* b) {
    asm volatile(
        "mma.sync.aligned.m16n8k16.row.col.f32.f16.f16.f32 "
        "{%0,%1,%2,%3}, {%4,%5,%6,%7}, {%8,%9}, {%0,%1,%2,%3};"
        : "+f"(d[0]), "+f"(d[1]), "+f"(d[2]), "+f"(d[3])
        : "r"(a[0]), "r"(a[1]), "r"(a[2]), "r"(a[3]), "r"(b[0]), "r"(b[1]));
}
__device__ __forceinline__ void cp_async16(uint32_t sdst, const void* gsrc) {
    asm volatile("cp.async.cg.shared.global [%0], [%1], 16;" :: "r"(sdst), "l"(gsrc));
}
__device__ __forceinline__ uint32_t smem_u32(const void* p) {
    uint32_t a;
    asm("{ .reg .u64 t; cvta.to.shared.u64 t, %1; cvt.u32.u64 %0, t; }" : "=r"(a) : "l"(p));
    return a;
}
__device__ __forceinline__ int chunk_of(int r) {
    return (r >= 27) ? 3 : (r >= 18) ? 2 : (r >= 9) ? 1 : 0;
}

// one shift-round of MMA work (warp tile 32 px x 64 couts)
__device__ __forceinline__ void compute_round(
    const char* smem, int chunk, int off, int bofs,
    int wm, int wn, int lane, float acc[2][8][4])
{
    const uint32_t* sA = (const uint32_t*)(smem + (chunk & 1) * SA_BYTES);
    const uint4* sB4 = (const uint4*)(smem + ABUFS + bofs);
    const int qb = off + wm * 32 + (lane >> 2);
    #pragma unroll
    for (int kt = 0; kt < 2; kt++) {
        const uint32_t* arow = sA + (kt * 8 + (lane & 3)) * AQ;
        uint32_t afr[2][4];
        #pragma unroll
        for (int mt = 0; mt < 2; mt++) {
            const int q = qb + mt * 16;
            afr[mt][0] = arow[q];
            afr[mt][1] = arow[q + 8];
            afr[mt][2] = arow[4 * AQ + q];
            afr[mt][3] = arow[4 * AQ + q + 8];
        }
        uint4 bfr[4];
        #pragma unroll
        for (int c4 = 0; c4 < 4; c4++)
            bfr[c4] = sB4[((wn * 4 + c4) * 2 + kt) * 32 + lane];
        #pragma unroll
        for (int mt = 0; mt < 2; mt++)
            #pragma unroll
            for (int c4 = 0; c4 < 4; c4++) {
                mma_f16(acc[mt][c4 * 2],     afr[mt], (const uint32_t*)&bfr[c4]);
                mma_f16(acc[mt][c4 * 2 + 1], afr[mt], ((const uint32_t*)&bfr[c4]) + 2);
            }
    }
}

// ---------------- main ----------------
__global__ void __launch_bounds__(256, 2)
conv_main(const float* __restrict__ bias, float* __restrict__ out) {
    extern __shared__ char smem[];
    const uint32_t smem_b = smem_u32(smem);
    const int tid  = threadIdx.x;
    const int lane = tid & 31;
    const int wid  = tid >> 5;
    const int wm   = wid & 3;          // 4 m-warps: 32 px each
    const int wn   = wid >> 2;         // 2 n-warps: 64 couts each
    const int bb   = blockIdx.z;
    const int nb   = blockIdx.y;       // 0/1
    const int q0   = blockIdx.x * 128;

    const __half2* xpbh = g_xpadh + (long)bb * 64 * CSTRIDE;

    float acc[2][8][4];
    #pragma unroll
    for (int i = 0; i < 2; i++)
        #pragma unroll
        for (int j = 0; j < 8; j++)
            #pragma unroll
            for (int k = 0; k < 4; k++) acc[i][j][k] = 0.0f;

    // A stage: 16 c2-rows x 62 x 16B into buffer sel
    #define STAGE_A(chunk, sel)                                                    \
        do {                                                                       \
            const __half2* asrc = xpbh + (long)((chunk) * 16) * CSTRIDE + q0;      \
            _Pragma("unroll")                                                      \
            for (int it = 0; it < 4; it++) {                                       \
                int aid = it * 256 + tid;                                          \
                if (aid < 16 * 62) {                                               \
                    int row = aid / 62, col = aid - row * 62;                      \
                    cp_async16(smem_b + (sel) * SA_BYTES + (row * AQ + col * 4) * 4, \
                               asrc + (long)row * CSTRIDE + col * 4);              \
                }                                                                  \
            }                                                                      \
        } while (0)

    // stage B for one shift-round r into quad buffer ((r>>2)&1), slot (r&3)
    #define STAGE_B1(r)                                                            \
        do {                                                                       \
            const int ch = chunk_of(r), sh = (r) - 9 * ch;                         \
            const uint32_t* src = g_wrfh                                           \
                + ((size_t)((nb * 4 + ch) * 9 + sh)) * 2048 + tid * 4;             \
            uint32_t dst = smem_b + ABUFS + (((r) >> 2) & 1) * SBQ_BYTES           \
                           + ((r) & 3) * 8192 + tid * 16;                          \
            cp_async16(dst, src);                                                  \
            cp_async16(dst + 4096, src + 1024);                                    \
        } while (0)

    // prologue: window 0 data (B rounds 0..3, A chunk 0 -> buf 0)
    STAGE_B1(0); STAGE_B1(1); STAGE_B1(2); STAGE_B1(3);
    STAGE_A(0, 0);
    asm volatile("cp.async.commit_group;" ::: "memory");

    for (int w = 0; w < NWIN; w++) {
        // wait for this window's data (committed one window ago)
        asm volatile("cp.async.wait_group 0;" ::: "memory");
        __syncthreads();

        // Window body: stage round r0+j just before computing round 4w+j,
        // spreading LSU/cp.async pressure across the window. One commit per
        // window (after the last stage). All staging remains post-barrier:
        // ring-2 safe (every warp past this barrier finished window w-1, the
        // only reader of buffer (w+1)%2). A: buf1 last read r17 (win 4) ->
        // staged win 5; buf0 last read r8 (win 2) -> staged win 3;
        // chunk1->buf1 staged win 0.
        const int qbase = (w & 1) * SBQ_BYTES;
        const bool more = (w + 1 < NWIN);
        const int r0 = 4 * (w + 1);
        #pragma unroll
        for (int j = 0; j < 4; j++) {
            if (more) {
                STAGE_B1(r0 + j);
                if (j == 0) {
                    if (w == 0)      STAGE_A(1, 1);
                    else if (w == 3) STAGE_A(2, 0);
                    else if (w == 5) STAGE_A(3, 1);
                }
                if (j == 3)
                    asm volatile("cp.async.commit_group;" ::: "memory");
            }
            const int r  = 4 * w + j;
            const int ch = chunk_of(r);
            const int s  = r - 9 * ch;
            compute_round(smem, ch, (s / 3) * PW + (s % 3), qbase + j * 8192,
                          wm, wn, lane, acc);
        }
    }

    // ---- epilogue ----
    const long obb = (long)bb * COUT * (HW * HW);
    #pragma unroll
    for (int nt = 0; nt < 8; nt++) {
        const int n = nb * 128 + wn * 64 + nt * 8 + (lane & 3) * 2;
        const float bv0 = __ldg(bias + n);
        const float bv1 = __ldg(bias + n + 1);
        const long onb = obb + (long)n * (HW * HW);
        #pragma unroll
        for (int mt = 0; mt < 2; mt++) {
            const int m = q0 + wm * 32 + mt * 16 + (lane >> 2);
            {
                const int h = m / PW, w = m % PW;
                if (h < HW && w < HW) {
                    const long o = onb + h * HW + w;
                    out[o]           = acc[mt][nt][0] + bv0;
                    out[o + HW * HW] = acc[mt][nt][1] + bv1;
                }
            }
            {
                const int m2 = m + 8;
                const int h = m2 / PW, w = m2 % PW;
                if (h < HW && w < HW) {
                    const long o = onb + h * HW + w;
                    out[o]           = acc[mt][nt][2] + bv0;
                    out[o + HW * HW] = acc[mt][nt][3] + bv1;
                }
            }
        }
    }
}

// ---------------- launch ----------------
extern "C" void kernel_launch(void* const* d_in, const int* in_sizes, int n_in,
                              void* d_out, int out_size) {
    const float* x  = (const float*)d_in[0];
    const float* W  = (const float*)d_in[1];
    const float* bi = (const float*)d_in[2];
    float* out      = (float*)d_out;

    cudaFuncSetAttribute(conv_main, cudaFuncAttributeMaxDynamicSharedMemorySize,
                         SMEM_TOTAL);

    const int prep_total = N_COPY + N_WRF;
    prep_kernel<<<(prep_total + 255) / 256, 256>>>(x, W);
    conv_main<<<dim3(MTILES, 2, BATCH), 256, SMEM_TOTAL>>>(bi, out);
}

// round 15
// speedup vs baseline: 1.4166x; 1.4166x over previous
#include <cuda_runtime.h>
#include <cuda_fp16.h>
#include <cstdint>

// ============================================================
// Conv2d 3x3 s1 p1: x(32,128,56,56)*W(256,128,3,3)+b -> (32,256,56,56)
// Shifted-GEMM conv on mma.sync.m16n8k16.f32.f16.f16.f32.
// FINAL (= R10, verified best 166.1us): 9 quad windows — ONE barrier +
// ONE cp.async group per FOUR shift-rounds. Staging issued AFTER the
// window barrier: B ring of 2 quad buffers is provably safe (writer
// (w+1)%2; all warps past the barrier finished window w-1, the only
// reader of that buffer). A double-buffered per 32-cin chunk (halo
// window 248 px, AQ=248), staged at windows 0/3/5.
// CTA = 128 px x 128 couts, 256 thr, 2 CTAs/SM. Warp tile 32x64
// (192 B/HMMA — the crossbar/occupancy optimum per R13 post-mortem).
// Perturbations tested and rejected: inline A staging from raw x (R11,
// +30us), staging reorder (R12, neutral), 32x32 tile @3 CTAs/SM (R13,
// +8us, L1 79%), interleaved staging + coarse prep (R14, +70us).
// ============================================================

#define HW        56
#define PW        58
#define CSTRIDE   3584          // half2 units per (b,c2) slice
#define CIN       128
#define COUT      256
#define BATCH     32
#define MTILES    26
#define NWIN      9             // 36 shift-rounds as 9 quad windows
#define AQ        248           // A smem q-stride (half2 units)
#define SA_BYTES  (16 * AQ * 4) // 15872 per A buffer
#define ABUFS     (2 * SA_BYTES)
#define SBQ_BYTES 32768         // B quad buffer (4 rounds x 8KB)
#define SMEM_TOTAL (ABUFS + 2 * SBQ_BYTES)   // 97280

__device__ __half2  g_xpadh[BATCH * 64 * CSTRIDE];
__device__ uint32_t g_wrfh[2 * 4 * 9 * 2048];

#define N_COPY (32 * 64 * 56 * 14)
#define N_BORD (32 * 64 * 448)
#define N_WRF  (2 * 4 * 9 * 2048)

// ---------------- fused prep ----------------
__global__ void prep_kernel(const float* __restrict__ x, const float* __restrict__ W) {
    int id = blockIdx.x * blockDim.x + threadIdx.x;
    if (id < N_COPY) {
        int f4  = id % 14;
        int h   = (id / 14) % 56;
        int bc2 = id / (14 * 56);
        const float* p0 = x + ((long)bc2 * 2) * 3136 + h * 56 + f4 * 4;
        float4 v0 = *(const float4*)p0;
        float4 v1 = *(const float4*)(p0 + 3136);
        __half2* d = g_xpadh + (long)bc2 * CSTRIDE + (h + 1) * PW + 1 + f4 * 4;
        d[0] = __floats2half2_rn(v0.x, v1.x);
        d[1] = __floats2half2_rn(v0.y, v1.y);
        d[2] = __floats2half2_rn(v0.z, v1.z);
        d[3] = __floats2half2_rn(v0.w, v1.w);
    } else if (id < N_COPY + N_BORD) {
        int t = id - N_COPY;
        int i = t % 448;
        long bc2 = t / 448;
        int pos;
        if (i < 58)       pos = i;
        else if (i < 116) pos = 57 * PW + (i - 58);
        else if (i < 228) {
            int j = i - 116;
            pos = (1 + (j >> 1)) * PW + ((j & 1) ? 57 : 0);
        } else            pos = PW * PW + (i - 228);
        g_xpadh[bc2 * CSTRIDE + pos] = __floats2half2_rn(0.f, 0.f);
    } else if (id < N_COPY + N_BORD + N_WRF) {
        int idx3 = id - N_COPY - N_BORD;
        int blk = idx3 >> 11, within = idx3 & 2047;
        int s = blk % 9, t = blk / 9;
        int chunk = t & 3, nb = t >> 2;
        int u4 = within >> 2, j = within & 3;
        int lane = u4 & 31, t2 = u4 >> 5;
        int kt = t2 & 1, p = t2 >> 1;
        int nt = p * 2 + (j >> 1), reg = j & 1;
        int n = nb * 128 + nt * 8 + (lane >> 2);
        int c = chunk * 32 + kt * 16 + (lane & 3) * 2 + reg * 8;
        __half2 hv = __floats2half2_rn(W[(n * CIN + c) * 9 + s],
                                       W[(n * CIN + c + 1) * 9 + s]);
        g_wrfh[idx3] = *(uint32_t*)&hv;
    }
}

// ---------------- helpers ----------------
__device__ __forceinline__ void mma_f16(float* d, const uint32_t* a, const uint32_t* b) {
    asm volatile(
        "mma.sync.aligned.m16n8k16.row.col.f32.f16.f16.f32 "
        "{%0,%1,%2,%3}, {%4,%5,%6,%7}, {%8,%9}, {%0,%1,%2,%3};"
        : "+f"(d[0]), "+f"(d[1]), "+f"(d[2]), "+f"(d[3])
        : "r"(a[0]), "r"(a[1]), "r"(a[2]), "r"(a[3]), "r"(b[0]), "r"(b[1]));
}
__device__ __forceinline__ void cp_async16(uint32_t sdst, const void* gsrc) {
    asm volatile("cp.async.cg.shared.global [%0], [%1], 16;" :: "r"(sdst), "l"(gsrc));
}
__device__ __forceinline__ uint32_t smem_u32(const void* p) {
    uint32_t a;
    asm("{ .reg .u64 t; cvta.to.shared.u64 t, %1; cvt.u32.u64 %0, t; }" : "=r"(a) : "l"(p));
    return a;
}
__device__ __forceinline__ int chunk_of(int r) {
    return (r >= 27) ? 3 : (r >= 18) ? 2 : (r >= 9) ? 1 : 0;
}

// one shift-round of MMA work
__device__ __forceinline__ void compute_round(
    const char* smem, int chunk, int off, int bofs,
    int wm, int wn, int lane, float acc[2][8][4])
{
    const uint32_t* sA = (const uint32_t*)(smem + (chunk & 1) * SA_BYTES);
    const uint4* sB4 = (const uint4*)(smem + ABUFS + bofs);
    const int qb = off + wm * 32 + (lane >> 2);
    #pragma unroll
    for (int kt = 0; kt < 2; kt++) {
        const uint32_t* arow = sA + (kt * 8 + (lane & 3)) * AQ;
        uint32_t afr[2][4];
        #pragma unroll
        for (int mt = 0; mt < 2; mt++) {
            const int q = qb + mt * 16;
            afr[mt][0] = arow[q];
            afr[mt][1] = arow[q + 8];
            afr[mt][2] = arow[4 * AQ + q];
            afr[mt][3] = arow[4 * AQ + q + 8];
        }
        uint4 bfr[4];
        #pragma unroll
        for (int c4 = 0; c4 < 4; c4++)
            bfr[c4] = sB4[((wn * 4 + c4) * 2 + kt) * 32 + lane];
        #pragma unroll
        for (int mt = 0; mt < 2; mt++)
            #pragma unroll
            for (int c4 = 0; c4 < 4; c4++) {
                mma_f16(acc[mt][c4 * 2],     afr[mt], (const uint32_t*)&bfr[c4]);
                mma_f16(acc[mt][c4 * 2 + 1], afr[mt], ((const uint32_t*)&bfr[c4]) + 2);
            }
    }
}

// ---------------- main ----------------
__global__ void __launch_bounds__(256, 2)
conv_main(const float* __restrict__ bias, float* __restrict__ out) {
    extern __shared__ char smem[];
    const uint32_t smem_b = smem_u32(smem);
    const int tid  = threadIdx.x;
    const int lane = tid & 31;
    const int wid  = tid >> 5;
    const int wm   = wid & 3;          // 4 m-warps: 32 px each
    const int wn   = wid >> 2;         // 2 n-warps: 64 couts each
    const int bb   = blockIdx.z;
    const int nb   = blockIdx.y;       // 0/1
    const int q0   = blockIdx.x * 128;

    const __half2* xpbh = g_xpadh + (long)bb * 64 * CSTRIDE;

    float acc[2][8][4];
    #pragma unroll
    for (int i = 0; i < 2; i++)
        #pragma unroll
        for (int j = 0; j < 8; j++)
            #pragma unroll
            for (int k = 0; k < 4; k++) acc[i][j][k] = 0.0f;

    // A stage: 16 c2-rows x 62 x 16B into buffer sel
    #define STAGE_A(chunk, sel)                                                    \
        do {                                                                       \
            const __half2* asrc = xpbh + (long)((chunk) * 16) * CSTRIDE + q0;      \
            _Pragma("unroll")                                                      \
            for (int it = 0; it < 4; it++) {                                       \
                int aid = it * 256 + tid;                                          \
                if (aid < 16 * 62) {                                               \
                    int row = aid / 62, col = aid - row * 62;                      \
                    cp_async16(smem_b + (sel) * SA_BYTES + (row * AQ + col * 4) * 4, \
                               asrc + (long)row * CSTRIDE + col * 4);              \
                }                                                                  \
            }                                                                      \
        } while (0)

    // stage B for one shift-round r into quad buffer ((r>>2)&1), slot (r&3)
    #define STAGE_B1(r)                                                            \
        do {                                                                       \
            const int ch = chunk_of(r), sh = (r) - 9 * ch;                         \
            const uint32_t* src = g_wrfh                                           \
                + ((size_t)((nb * 4 + ch) * 9 + sh)) * 2048 + tid * 4;             \
            uint32_t dst = smem_b + ABUFS + (((r) >> 2) & 1) * SBQ_BYTES           \
                           + ((r) & 3) * 8192 + tid * 16;                          \
            cp_async16(dst, src);                                                  \
            cp_async16(dst + 4096, src + 1024);                                    \
        } while (0)

    // prologue: window 0 data (B rounds 0..3, A chunk 0 -> buf 0)
    STAGE_B1(0); STAGE_B1(1); STAGE_B1(2); STAGE_B1(3);
    STAGE_A(0, 0);
    asm volatile("cp.async.commit_group;" ::: "memory");

    for (int w = 0; w < NWIN; w++) {
        // wait for this window's data (committed one window ago)
        asm volatile("cp.async.wait_group 0;" ::: "memory");
        __syncthreads();

        // stage next window AFTER the barrier: ring-2 is safe because every
        // warp past this barrier finished window w-1, the only reader of
        // target buffer (w+1)%2. A targets: buf1 last read r17 (win 4) ->
        // staged at win 5; buf0 last read r8 (win 2) -> staged at win 3.
        if (w + 1 < NWIN) {
            const int r0 = 4 * (w + 1);
            STAGE_B1(r0); STAGE_B1(r0 + 1); STAGE_B1(r0 + 2); STAGE_B1(r0 + 3);
            if (w == 0)      STAGE_A(1, 1);
            else if (w == 3) STAGE_A(2, 0);
            else if (w == 5) STAGE_A(3, 1);
            asm volatile("cp.async.commit_group;" ::: "memory");
        }

        // compute rounds 4w .. 4w+3
        const int qbase = (w & 1) * SBQ_BYTES;
        #pragma unroll
        for (int j = 0; j < 4; j++) {
            const int r  = 4 * w + j;
            const int ch = chunk_of(r);
            const int s  = r - 9 * ch;
            compute_round(smem, ch, (s / 3) * PW + (s % 3), qbase + j * 8192,
                          wm, wn, lane, acc);
        }
    }

    // ---- epilogue ----
    const long obb = (long)bb * COUT * (HW * HW);
    #pragma unroll
    for (int nt = 0; nt < 8; nt++) {
        const int n = nb * 128 + wn * 64 + nt * 8 + (lane & 3) * 2;
        const float bv0 = __ldg(bias + n);
        const float bv1 = __ldg(bias + n + 1);
        const long onb = obb + (long)n * (HW * HW);
        #pragma unroll
        for (int mt = 0; mt < 2; mt++) {
            const int m = q0 + wm * 32 + mt * 16 + (lane >> 2);
            {
                const int h = m / PW, w = m % PW;
                if (h < HW && w < HW) {
                    const long o = onb + h * HW + w;
                    out[o]           = acc[mt][nt][0] + bv0;
                    out[o + HW * HW] = acc[mt][nt][1] + bv1;
                }
            }
            {
                const int m2 = m + 8;
                const int h = m2 / PW, w = m2 % PW;
                if (h < HW && w < HW) {
                    const long o = onb + h * HW + w;
                    out[o]           = acc[mt][nt][2] + bv0;
                    out[o + HW * HW] = acc[mt][nt][3] + bv1;
                }
            }
        }
    }
}

// ---------------- launch ----------------
extern "C" void kernel_launch(void* const* d_in, const int* in_sizes, int n_in,
                              void* d_out, int out_size) {
    const float* x  = (const float*)d_in[0];
    const float* W  = (const float*)d_in[1];
    const float* bi = (const float*)d_in[2];
    float* out      = (float*)d_out;

    cudaFuncSetAttribute(conv_main, cudaFuncAttributeMaxDynamicSharedMemorySize,
                         SMEM_TOTAL);

    const int prep_total = N_COPY + N_BORD + N_WRF;
    prep_kernel<<<(prep_total + 255) / 256, 256>>>(x, W);
    conv_main<<<dim3(MTILES, 2, BATCH), 256, SMEM_TOTAL>>>(bi, out);
}

// round 16
// speedup vs baseline: 1.4240x; 1.0052x over previous
#include <cuda_runtime.h>
#include <cuda_fp16.h>
#include <cstdint>

// ============================================================
// Conv2d 3x3 s1 p1: x(32,128,56,56)*W(256,128,3,3)+b -> (32,256,56,56)
// Shifted-GEMM conv on mma.sync.m16n8k16.f32.f16.f16.f32.
// R16 = R10 conv_main (verified best, 149.5-150.6us) + R12 border-free
// prep (verified: device globals zero-init at load; interior copy never
// touches border/slack cells, so the zero halo persists across graph
// replays). Both halves independently verified at rel_err 2.824e-4.
//
// Mainloop: 9 quad windows — ONE barrier + ONE cp.async group per FOUR
// shift-rounds. Staging strictly post-barrier: B ring of 2 quad buffers
// (writer (w+1)%2; all warps past the barrier finished window w-1, the
// only reader). A double-buffered per 32-cin chunk (halo 248 px,
// AQ=248), staged at windows 0/3/5. CTA = 128 px x 128 couts, 256 thr,
// 2 CTAs/SM, warp tile 32x64 (192 B/HMMA crossbar/occupancy optimum).
// ============================================================

#define HW        56
#define PW        58
#define CSTRIDE   3584          // half2 units per (b,c2) slice
#define CIN       128
#define COUT      256
#define BATCH     32
#define MTILES    26
#define NWIN      9             // 36 shift-rounds as 9 quad windows
#define AQ        248           // A smem q-stride (half2 units)
#define SA_BYTES  (16 * AQ * 4) // 15872 per A buffer
#define ABUFS     (2 * SA_BYTES)
#define SBQ_BYTES 32768         // B quad buffer (4 rounds x 8KB)
#define SMEM_TOTAL (ABUFS + 2 * SBQ_BYTES)   // 97280

__device__ __half2  g_xpadh[BATCH * 64 * CSTRIDE];   // zero-init at load;
                                                     // border/slack never written
__device__ uint32_t g_wrfh[2 * 4 * 9 * 2048];        // W fragment order (half2)

#define N_COPY (32 * 64 * 56 * 14)
#define N_WRF  (2 * 4 * 9 * 2048)

// ---------------- fused prep: interior copy + W fragments ----------------
__global__ void prep_kernel(const float* __restrict__ x, const float* __restrict__ W) {
    int id = blockIdx.x * blockDim.x + threadIdx.x;
    if (id < N_COPY) {
        int f4  = id % 14;
        int h   = (id / 14) % 56;
        int bc2 = id / (14 * 56);          // b*64 + c2
        const float* p0 = x + ((long)bc2 * 2) * 3136 + h * 56 + f4 * 4;
        float4 v0 = *(const float4*)p0;
        float4 v1 = *(const float4*)(p0 + 3136);
        __half2* d = g_xpadh + (long)bc2 * CSTRIDE + (h + 1) * PW + 1 + f4 * 4;
        d[0] = __floats2half2_rn(v0.x, v1.x);
        d[1] = __floats2half2_rn(v0.y, v1.y);
        d[2] = __floats2half2_rn(v0.z, v1.z);
        d[3] = __floats2half2_rn(v0.w, v1.w);
    } else if (id < N_COPY + N_WRF) {
        // g_wrfh: block = (nb*4+chunk)*9+s, u4 = ((p*2+kt)*32+lane), word j:
        //   nt = p*2+(j>>1), reg = j&1
        //   half2 = (W[n][c], W[n][c+1]), n = nb*128+nt*8+lane/4,
        //   c = chunk*32 + kt*16 + (lane&3)*2 + reg*8
        int idx3 = id - N_COPY;
        int blk = idx3 >> 11, within = idx3 & 2047;
        int s = blk % 9, t = blk / 9;
        int chunk = t & 3, nb = t >> 2;
        int u4 = within >> 2, j = within & 3;
        int lane = u4 & 31, t2 = u4 >> 5;
        int kt = t2 & 1, p = t2 >> 1;
        int nt = p * 2 + (j >> 1), reg = j & 1;
        int n = nb * 128 + nt * 8 + (lane >> 2);
        int c = chunk * 32 + kt * 16 + (lane & 3) * 2 + reg * 8;
        __half2 hv = __floats2half2_rn(W[(n * CIN + c) * 9 + s],
                                       W[(n * CIN + c + 1) * 9 + s]);
        g_wrfh[idx3] = *(uint32_t*)&hv;
    }
}

// ---------------- helpers ----------------
__device__ __forceinline__ void mma_f16(float* d, const uint32_t* a, const uint32_t* b) {
    asm volatile(
        "mma.sync.aligned.m16n8k16.row.col.f32.f16.f16.f32 "
        "{%0,%1,%2,%3}, {%4,%5,%6,%7}, {%8,%9}, {%0,%1,%2,%3};"
        : "+f"(d[0]), "+f"(d[1]), "+f"(d[2]), "+f"(d[3])
        : "r"(a[0]), "r"(a[1]), "r"(a[2]), "r"(a[3]), "r"(b[0]), "r"(b[1]));
}
__device__ __forceinline__ void cp_async16(uint32_t sdst, const void* gsrc) {
    asm volatile("cp.async.cg.shared.global [%0], [%1], 16;" :: "r"(sdst), "l"(gsrc));
}
__device__ __forceinline__ uint32_t smem_u32(const void* p) {
    uint32_t a;
    asm("{ .reg .u64 t; cvta.to.shared.u64 t, %1; cvt.u32.u64 %0, t; }" : "=r"(a) : "l"(p));
    return a;
}
__device__ __forceinline__ int chunk_of(int r) {
    return (r >= 27) ? 3 : (r >= 18) ? 2 : (r >= 9) ? 1 : 0;
}

// one shift-round of MMA work (warp tile 32 px x 64 couts)
__device__ __forceinline__ void compute_round(
    const char* smem, int chunk, int off, int bofs,
    int wm, int wn, int lane, float acc[2][8][4])
{
    const uint32_t* sA = (const uint32_t*)(smem + (chunk & 1) * SA_BYTES);
    const uint4* sB4 = (const uint4*)(smem + ABUFS + bofs);
    const int qb = off + wm * 32 + (lane >> 2);
    #pragma unroll
    for (int kt = 0; kt < 2; kt++) {
        const uint32_t* arow = sA + (kt * 8 + (lane & 3)) * AQ;
        uint32_t afr[2][4];
        #pragma unroll
        for (int mt = 0; mt < 2; mt++) {
            const int q = qb + mt * 16;
            afr[mt][0] = arow[q];
            afr[mt][1] = arow[q + 8];
            afr[mt][2] = arow[4 * AQ + q];
            afr[mt][3] = arow[4 * AQ + q + 8];
        }
        uint4 bfr[4];
        #pragma unroll
        for (int c4 = 0; c4 < 4; c4++)
            bfr[c4] = sB4[((wn * 4 + c4) * 2 + kt) * 32 + lane];
        #pragma unroll
        for (int mt = 0; mt < 2; mt++)
            #pragma unroll
            for (int c4 = 0; c4 < 4; c4++) {
                mma_f16(acc[mt][c4 * 2],     afr[mt], (const uint32_t*)&bfr[c4]);
                mma_f16(acc[mt][c4 * 2 + 1], afr[mt], ((const uint32_t*)&bfr[c4]) + 2);
            }
    }
}

// ---------------- main ----------------
__global__ void __launch_bounds__(256, 2)
conv_main(const float* __restrict__ bias, float* __restrict__ out) {
    extern __shared__ char smem[];
    const uint32_t smem_b = smem_u32(smem);
    const int tid  = threadIdx.x;
    const int lane = tid & 31;
    const int wid  = tid >> 5;
    const int wm   = wid & 3;          // 4 m-warps: 32 px each
    const int wn   = wid >> 2;         // 2 n-warps: 64 couts each
    const int bb   = blockIdx.z;
    const int nb   = blockIdx.y;       // 0/1
    const int q0   = blockIdx.x * 128;

    const __half2* xpbh = g_xpadh + (long)bb * 64 * CSTRIDE;

    float acc[2][8][4];
    #pragma unroll
    for (int i = 0; i < 2; i++)
        #pragma unroll
        for (int j = 0; j < 8; j++)
            #pragma unroll
            for (int k = 0; k < 4; k++) acc[i][j][k] = 0.0f;

    // A stage: 16 c2-rows x 62 x 16B into buffer sel
    #define STAGE_A(chunk, sel)                                                    \
        do {                                                                       \
            const __half2* asrc = xpbh + (long)((chunk) * 16) * CSTRIDE + q0;      \
            _Pragma("unroll")                                                      \
            for (int it = 0; it < 4; it++) {                                       \
                int aid = it * 256 + tid;                                          \
                if (aid < 16 * 62) {                                               \
                    int row = aid / 62, col = aid - row * 62;                      \
                    cp_async16(smem_b + (sel) * SA_BYTES + (row * AQ + col * 4) * 4, \
                               asrc + (long)row * CSTRIDE + col * 4);              \
                }                                                                  \
            }                                                                      \
        } while (0)

    // stage B for one shift-round r into quad buffer ((r>>2)&1), slot (r&3)
    #define STAGE_B1(r)                                                            \
        do {                                                                       \
            const int ch = chunk_of(r), sh = (r) - 9 * ch;                         \
            const uint32_t* src = g_wrfh                                           \
                + ((size_t)((nb * 4 + ch) * 9 + sh)) * 2048 + tid * 4;             \
            uint32_t dst = smem_b + ABUFS + (((r) >> 2) & 1) * SBQ_BYTES           \
                           + ((r) & 3) * 8192 + tid * 16;                          \
            cp_async16(dst, src);                                                  \
            cp_async16(dst + 4096, src + 1024);                                    \
        } while (0)

    // prologue: window 0 data (B rounds 0..3, A chunk 0 -> buf 0)
    STAGE_B1(0); STAGE_B1(1); STAGE_B1(2); STAGE_B1(3);
    STAGE_A(0, 0);
    asm volatile("cp.async.commit_group;" ::: "memory");

    for (int w = 0; w < NWIN; w++) {
        // wait for this window's data (committed one window ago)
        asm volatile("cp.async.wait_group 0;" ::: "memory");
        __syncthreads();

        // stage next window AFTER the barrier: ring-2 is safe because every
        // warp past this barrier finished window w-1, the only reader of
        // target buffer (w+1)%2. A targets: buf1 last read r17 (win 4) ->
        // staged at win 5; buf0 last read r8 (win 2) -> staged at win 3.
        if (w + 1 < NWIN) {
            const int r0 = 4 * (w + 1);
            STAGE_B1(r0); STAGE_B1(r0 + 1); STAGE_B1(r0 + 2); STAGE_B1(r0 + 3);
            if (w == 0)      STAGE_A(1, 1);
            else if (w == 3) STAGE_A(2, 0);
            else if (w == 5) STAGE_A(3, 1);
            asm volatile("cp.async.commit_group;" ::: "memory");
        }

        // compute rounds 4w .. 4w+3
        const int qbase = (w & 1) * SBQ_BYTES;
        #pragma unroll
        for (int j = 0; j < 4; j++) {
            const int r  = 4 * w + j;
            const int ch = chunk_of(r);
            const int s  = r - 9 * ch;
            compute_round(smem, ch, (s / 3) * PW + (s % 3), qbase + j * 8192,
                          wm, wn, lane, acc);
        }
    }

    // ---- epilogue ----
    const long obb = (long)bb * COUT * (HW * HW);
    #pragma unroll
    for (int nt = 0; nt < 8; nt++) {
        const int n = nb * 128 + wn * 64 + nt * 8 + (lane & 3) * 2;
        const float bv0 = __ldg(bias + n);
        const float bv1 = __ldg(bias + n + 1);
        const long onb = obb + (long)n * (HW * HW);
        #pragma unroll
        for (int mt = 0; mt < 2; mt++) {
            const int m = q0 + wm * 32 + mt * 16 + (lane >> 2);
            {
                const int h = m / PW, w = m % PW;
                if (h < HW && w < HW) {
                    const long o = onb + h * HW + w;
                    out[o]           = acc[mt][nt][0] + bv0;
                    out[o + HW * HW] = acc[mt][nt][1] + bv1;
                }
            }
            {
                const int m2 = m + 8;
                const int h = m2 / PW, w = m2 % PW;
                if (h < HW && w < HW) {
                    const long o = onb + h * HW + w;
                    out[o]           = acc[mt][nt][2] + bv0;
                    out[o + HW * HW] = acc[mt][nt][3] + bv1;
                }
            }
        }
    }
}

// ---------------- launch ----------------
extern "C" void kernel_launch(void* const* d_in, const int* in_sizes, int n_in,
                              void* d_out, int out_size) {
    const float* x  = (const float*)d_in[0];
    const float* W  = (const float*)d_in[1];
    const float* bi = (const float*)d_in[2];
    float* out      = (float*)d_out;

    cudaFuncSetAttribute(conv_main, cudaFuncAttributeMaxDynamicSharedMemorySize,
                         SMEM_TOTAL);

    const int prep_total = N_COPY + N_WRF;
    prep_kernel<<<(prep_total + 255) / 256, 256>>>(x, W);
    conv_main<<<dim3(MTILES, 2, BATCH), 256, SMEM_TOTAL>>>(bi, out);
}

// round 17
// speedup vs baseline: 1.4557x; 1.0223x over previous
#include <cuda_runtime.h>
#include <cuda_fp16.h>
#include <cstdint>

// ============================================================
// Conv2d 3x3 s1 p1: x(32,128,56,56)*W(256,128,3,3)+b -> (32,256,56,56)
// Shifted-GEMM conv on mma.sync.m16n8k16.f32.f16.f16.f32.
// R17 = R16 (verified best, 165.9us) + st.global.cs (evict-first) on
// the write-once output stream, protecting L2 residency of g_xpadh
// (29.4MB, re-read ~9x per batch slice) and g_wrfh (0.6MB, re-read
// 72x per CTA). Pure cache hint: no schedule/barrier/ring change.
//
// Mainloop: 9 quad windows — ONE barrier + ONE cp.async group per FOUR
// shift-rounds. Staging strictly post-barrier: B ring of 2 quad buffers
// (writer (w+1)%2; all warps past the barrier finished window w-1, the
// only reader). A double-buffered per 32-cin chunk (halo 248 px,
// AQ=248), staged at windows 0/3/5. CTA = 128 px x 128 couts, 256 thr,
// 2 CTAs/SM, warp tile 32x64 (192 B/HMMA crossbar/occupancy optimum).
// Border/slack of g_xpadh: zero-initialized at module load, never
// written -> persists across graph replays (verified R12/R16).
// ============================================================

#define HW        56
#define PW        58
#define CSTRIDE   3584          // half2 units per (b,c2) slice
#define CIN       128
#define COUT      256
#define BATCH     32
#define MTILES    26
#define NWIN      9             // 36 shift-rounds as 9 quad windows
#define AQ        248           // A smem q-stride (half2 units)
#define SA_BYTES  (16 * AQ * 4) // 15872 per A buffer
#define ABUFS     (2 * SA_BYTES)
#define SBQ_BYTES 32768         // B quad buffer (4 rounds x 8KB)
#define SMEM_TOTAL (ABUFS + 2 * SBQ_BYTES)   // 97280

__device__ __half2  g_xpadh[BATCH * 64 * CSTRIDE];   // zero-init at load;
                                                     // border/slack never written
__device__ uint32_t g_wrfh[2 * 4 * 9 * 2048];        // W fragment order (half2)

#define N_COPY (32 * 64 * 56 * 14)
#define N_WRF  (2 * 4 * 9 * 2048)

// ---------------- fused prep: interior copy + W fragments ----------------
__global__ void prep_kernel(const float* __restrict__ x, const float* __restrict__ W) {
    int id = blockIdx.x * blockDim.x + threadIdx.x;
    if (id < N_COPY) {
        int f4  = id % 14;
        int h   = (id / 14) % 56;
        int bc2 = id / (14 * 56);          // b*64 + c2
        const float* p0 = x + ((long)bc2 * 2) * 3136 + h * 56 + f4 * 4;
        float4 v0 = *(const float4*)p0;
        float4 v1 = *(const float4*)(p0 + 3136);
        __half2* d = g_xpadh + (long)bc2 * CSTRIDE + (h + 1) * PW + 1 + f4 * 4;
        d[0] = __floats2half2_rn(v0.x, v1.x);
        d[1] = __floats2half2_rn(v0.y, v1.y);
        d[2] = __floats2half2_rn(v0.z, v1.z);
        d[3] = __floats2half2_rn(v0.w, v1.w);
    } else if (id < N_COPY + N_WRF) {
        // g_wrfh: block = (nb*4+chunk)*9+s, u4 = ((p*2+kt)*32+lane), word j:
        //   nt = p*2+(j>>1), reg = j&1
        //   half2 = (W[n][c], W[n][c+1]), n = nb*128+nt*8+lane/4,
        //   c = chunk*32 + kt*16 + (lane&3)*2 + reg*8
        int idx3 = id - N_COPY;
        int blk = idx3 >> 11, within = idx3 & 2047;
        int s = blk % 9, t = blk / 9;
        int chunk = t & 3, nb = t >> 2;
        int u4 = within >> 2, j = within & 3;
        int lane = u4 & 31, t2 = u4 >> 5;
        int kt = t2 & 1, p = t2 >> 1;
        int nt = p * 2 + (j >> 1), reg = j & 1;
        int n = nb * 128 + nt * 8 + (lane >> 2);
        int c = chunk * 32 + kt * 16 + (lane & 3) * 2 + reg * 8;
        __half2 hv = __floats2half2_rn(W[(n * CIN + c) * 9 + s],
                                       W[(n * CIN + c + 1) * 9 + s]);
        g_wrfh[idx3] = *(uint32_t*)&hv;
    }
}

// ---------------- helpers ----------------
__device__ __forceinline__ void mma_f16(float* d, const uint32_t* a, const uint32_t* b) {
    asm volatile(
        "mma.sync.aligned.m16n8k16.row.col.f32.f16.f16.f32 "
        "{%0,%1,%2,%3}, {%4,%5,%6,%7}, {%8,%9}, {%0,%1,%2,%3};"
        : "+f"(d[0]), "+f"(d[1]), "+f"(d[2]), "+f"(d[3])
        : "r"(a[0]), "r"(a[1]), "r"(a[2]), "r"(a[3]), "r"(b[0]), "r"(b[1]));
}
__device__ __forceinline__ void cp_async16(uint32_t sdst, const void* gsrc) {
    asm volatile("cp.async.cg.shared.global [%0], [%1], 16;" :: "r"(sdst), "l"(gsrc));
}
__device__ __forceinline__ uint32_t smem_u32(const void* p) {
    uint32_t a;
    asm("{ .reg .u64 t; cvta.to.shared.u64 t, %1; cvt.u32.u64 %0, t; }" : "=r"(a) : "l"(p));
    return a;
}
__device__ __forceinline__ void stg_cs(float* p, float v) {
    asm volatile("st.global.cs.f32 [%0], %1;" :: "l"(p), "f"(v) : "memory");
}
__device__ __forceinline__ int chunk_of(int r) {
    return (r >= 27) ? 3 : (r >= 18) ? 2 : (r >= 9) ? 1 : 0;
}

// one shift-round of MMA work (warp tile 32 px x 64 couts)
__device__ __forceinline__ void compute_round(
    const char* smem, int chunk, int off, int bofs,
    int wm, int wn, int lane, float acc[2][8][4])
{
    const uint32_t* sA = (const uint32_t*)(smem + (chunk & 1) * SA_BYTES);
    const uint4* sB4 = (const uint4*)(smem + ABUFS + bofs);
    const int qb = off + wm * 32 + (lane >> 2);
    #pragma unroll
    for (int kt = 0; kt < 2; kt++) {
        const uint32_t* arow = sA + (kt * 8 + (lane & 3)) * AQ;
        uint32_t afr[2][4];
        #pragma unroll
        for (int mt = 0; mt < 2; mt++) {
            const int q = qb + mt * 16;
            afr[mt][0] = arow[q];
            afr[mt][1] = arow[q + 8];
            afr[mt][2] = arow[4 * AQ + q];
            afr[mt][3] = arow[4 * AQ + q + 8];
        }
        uint4 bfr[4];
        #pragma unroll
        for (int c4 = 0; c4 < 4; c4++)
            bfr[c4] = sB4[((wn * 4 + c4) * 2 + kt) * 32 + lane];
        #pragma unroll
        for (int mt = 0; mt < 2; mt++)
            #pragma unroll
            for (int c4 = 0; c4 < 4; c4++) {
                mma_f16(acc[mt][c4 * 2],     afr[mt], (const uint32_t*)&bfr[c4]);
                mma_f16(acc[mt][c4 * 2 + 1], afr[mt], ((const uint32_t*)&bfr[c4]) + 2);
            }
    }
}

// ---------------- main ----------------
__global__ void __launch_bounds__(256, 2)
conv_main(const float* __restrict__ bias, float* __restrict__ out) {
    extern __shared__ char smem[];
    const uint32_t smem_b = smem_u32(smem);
    const int tid  = threadIdx.x;
    const int lane = tid & 31;
    const int wid  = tid >> 5;
    const int wm   = wid & 3;          // 4 m-warps: 32 px each
    const int wn   = wid >> 2;         // 2 n-warps: 64 couts each
    const int bb   = blockIdx.z;
    const int nb   = blockIdx.y;       // 0/1
    const int q0   = blockIdx.x * 128;

    const __half2* xpbh = g_xpadh + (long)bb * 64 * CSTRIDE;

    float acc[2][8][4];
    #pragma unroll
    for (int i = 0; i < 2; i++)
        #pragma unroll
        for (int j = 0; j < 8; j++)
            #pragma unroll
            for (int k = 0; k < 4; k++) acc[i][j][k] = 0.0f;

    // A stage: 16 c2-rows x 62 x 16B into buffer sel
    #define STAGE_A(chunk, sel)                                                    \
        do {                                                                       \
            const __half2* asrc = xpbh + (long)((chunk) * 16) * CSTRIDE + q0;      \
            _Pragma("unroll")                                                      \
            for (int it = 0; it < 4; it++) {                                       \
                int aid = it * 256 + tid;                                          \
                if (aid < 16 * 62) {                                               \
                    int row = aid / 62, col = aid - row * 62;                      \
                    cp_async16(smem_b + (sel) * SA_BYTES + (row * AQ + col * 4) * 4, \
                               asrc + (long)row * CSTRIDE + col * 4);              \
                }                                                                  \
            }                                                                      \
        } while (0)

    // stage B for one shift-round r into quad buffer ((r>>2)&1), slot (r&3)
    #define STAGE_B1(r)                                                            \
        do {                                                                       \
            const int ch = chunk_of(r), sh = (r) - 9 * ch;                         \
            const uint32_t* src = g_wrfh                                           \
                + ((size_t)((nb * 4 + ch) * 9 + sh)) * 2048 + tid * 4;             \
            uint32_t dst = smem_b + ABUFS + (((r) >> 2) & 1) * SBQ_BYTES           \
                           + ((r) & 3) * 8192 + tid * 16;                          \
            cp_async16(dst, src);                                                  \
            cp_async16(dst + 4096, src + 1024);                                    \
        } while (0)

    // prologue: window 0 data (B rounds 0..3, A chunk 0 -> buf 0)
    STAGE_B1(0); STAGE_B1(1); STAGE_B1(2); STAGE_B1(3);
    STAGE_A(0, 0);
    asm volatile("cp.async.commit_group;" ::: "memory");

    for (int w = 0; w < NWIN; w++) {
        // wait for this window's data (committed one window ago)
        asm volatile("cp.async.wait_group 0;" ::: "memory");
        __syncthreads();

        // stage next window AFTER the barrier: ring-2 is safe because every
        // warp past this barrier finished window w-1, the only reader of
        // target buffer (w+1)%2. A targets: buf1 last read r17 (win 4) ->
        // staged at win 5; buf0 last read r8 (win 2) -> staged at win 3.
        if (w + 1 < NWIN) {
            const int r0 = 4 * (w + 1);
            STAGE_B1(r0); STAGE_B1(r0 + 1); STAGE_B1(r0 + 2); STAGE_B1(r0 + 3);
            if (w == 0)      STAGE_A(1, 1);
            else if (w == 3) STAGE_A(2, 0);
            else if (w == 5) STAGE_A(3, 1);
            asm volatile("cp.async.commit_group;" ::: "memory");
        }

        // compute rounds 4w .. 4w+3
        const int qbase = (w & 1) * SBQ_BYTES;
        #pragma unroll
        for (int j = 0; j < 4; j++) {
            const int r  = 4 * w + j;
            const int ch = chunk_of(r);
            const int s  = r - 9 * ch;
            compute_round(smem, ch, (s / 3) * PW + (s % 3), qbase + j * 8192,
                          wm, wn, lane, acc);
        }
    }

    // ---- epilogue: evict-first stores (output is write-once) ----
    const long obb = (long)bb * COUT * (HW * HW);
    #pragma unroll
    for (int nt = 0; nt < 8; nt++) {
        const int n = nb * 128 + wn * 64 + nt * 8 + (lane & 3) * 2;
        const float bv0 = __ldg(bias + n);
        const float bv1 = __ldg(bias + n + 1);
        const long onb = obb + (long)n * (HW * HW);
        #pragma unroll
        for (int mt = 0; mt < 2; mt++) {
            const int m = q0 + wm * 32 + mt * 16 + (lane >> 2);
            {
                const int h = m / PW, w = m % PW;
                if (h < HW && w < HW) {
                    const long o = onb + h * HW + w;
                    stg_cs(out + o,           acc[mt][nt][0] + bv0);
                    stg_cs(out + o + HW * HW, acc[mt][nt][1] + bv1);
                }
            }
            {
                const int m2 = m + 8;
                const int h = m2 / PW, w = m2 % PW;
                if (h < HW && w < HW) {
                    const long o = onb + h * HW + w;
                    stg_cs(out + o,           acc[mt][nt][2] + bv0);
                    stg_cs(out + o + HW * HW, acc[mt][nt][3] + bv1);
                }
            }
        }
    }
}

// ---------------- launch ----------------
extern "C" void kernel_launch(void* const* d_in, const int* in_sizes, int n_in,
                              void* d_out, int out_size) {
    const float* x  = (const float*)d_in[0];
    const float* W  = (const float*)d_in[1];
    const float* bi = (const float*)d_in[2];
    float* out      = (float*)d_out;

    cudaFuncSetAttribute(conv_main, cudaFuncAttributeMaxDynamicSharedMemorySize,
                         SMEM_TOTAL);

    const int prep_total = N_COPY + N_WRF;
    prep_kernel<<<(prep_total + 255) / 256, 256>>>(x, W);
    conv_main<<<dim3(MTILES, 2, BATCH), 256, SMEM_TOTAL>>>(bi, out);
}